// round 6
// baseline (speedup 1.0000x reference)
#include <cuda_runtime.h>
#include <math.h>

#define SQ 2048
#define NB 8
#define HDIM 768
#define HD 384
#define NG 1536
#define NT 64
#define NU 32

// ---------------- device scratch (static, no runtime alloc) ----------------
__device__ float    g_xproj[2u * SQ * NB * NG];   // [dir][t][b][gate_row]  ~201 MB
__device__ float    g_hbuf [2 * 2 * NB * HD];     // [dir][buf][b][j]
__device__ unsigned g_flag [2 * 64 * 32];         // one 128B line per (dir, cta)
__device__ float    g_mp   [NB * NU * HDIM];      // [b][u][h] pooled features
__device__ float    g_emb  [NB * NU * HDIM];      // [b][u][h] routed embeddings

// ---------------- f32x2 packed-FMA helper (operands loaded pre-paired) -----
__device__ __forceinline__ unsigned long long fma2(
    unsigned long long a, unsigned long long b, unsigned long long c) {
    unsigned long long d;
    asm("fma.rn.f32x2 %0, %1, %2, %3;" : "=l"(d) : "l"(a), "l"(b), "l"(c));
    return d;
}
__device__ __forceinline__ float2 upk2(unsigned long long v) {
    float2 f;
    asm("mov.b64 {%0,%1}, %2;" : "=f"(f.x), "=f"(f.y) : "l"(v));
    return f;
}

// ---------------- pad kernel: ncu capture lands on launch #4 = k_lstm ------
__global__ void k_pad() {}

// ---------------- flag reset (graph replays must be deterministic) ---------
__global__ void k_reset()
{
    int i = blockIdx.x * 256 + threadIdx.x;
    if (i < 2 * 64 * 32) g_flag[i] = 0u;
}

// ---------------- K1: input projection GEMM (both directions) --------------
// (R1 version — known good)
__global__ void __launch_bounds__(256) k_gemm(
    const float* __restrict__ X,
    const float* __restrict__ Wf, const float* __restrict__ Wb,
    const float* __restrict__ bihf, const float* __restrict__ bhhf,
    const float* __restrict__ bihb, const float* __restrict__ bhhb)
{
    const int dir = blockIdx.z;
    const float* W = dir ? Wb : Wf;
    const int n0 = blockIdx.x * 128;
    const int m0 = blockIdx.y * 128;

    __shared__ float As[8][128];
    __shared__ float Bs[8][128];

    const int tid = threadIdx.x;
    const int lr = tid >> 1, lh = tid & 1;
    const int tx = tid & 15, ty = tid >> 4;

    float acc[8][8];
#pragma unroll
    for (int i = 0; i < 8; i++)
#pragma unroll
        for (int j = 0; j < 8; j++) acc[i][j] = 0.f;

    const float* xptr = X + (m0 + lr) * 768 + lh * 4;
    const float* wptr = W + (n0 + lr) * 768 + lh * 4;

    for (int kt = 0; kt < 768; kt += 8) {
        float4 av = *(const float4*)(xptr + kt);
        float4 bv = *(const float4*)(wptr + kt);
        __syncthreads();
        As[lh * 4 + 0][lr] = av.x; As[lh * 4 + 1][lr] = av.y;
        As[lh * 4 + 2][lr] = av.z; As[lh * 4 + 3][lr] = av.w;
        Bs[lh * 4 + 0][lr] = bv.x; Bs[lh * 4 + 1][lr] = bv.y;
        Bs[lh * 4 + 2][lr] = bv.z; Bs[lh * 4 + 3][lr] = bv.w;
        __syncthreads();
#pragma unroll
        for (int k = 0; k < 8; k++) {
            float a[8], b[8];
            *(float4*)(a)     = *(const float4*)&As[k][ty * 8];
            *(float4*)(a + 4) = *(const float4*)&As[k][ty * 8 + 4];
            *(float4*)(b)     = *(const float4*)&Bs[k][tx * 8];
            *(float4*)(b + 4) = *(const float4*)&Bs[k][tx * 8 + 4];
#pragma unroll
            for (int i = 0; i < 8; i++)
#pragma unroll
                for (int j = 0; j < 8; j++)
                    acc[i][j] = fmaf(a[i], b[j], acc[i][j]);
        }
    }

    const float* bi = dir ? bihb : bihf;
    const float* bh = dir ? bhhb : bhhf;
    float bias[8];
#pragma unroll
    for (int j = 0; j < 8; j++) {
        int n = n0 + tx * 8 + j;
        bias[j] = bi[n] + bh[n];
    }
#pragma unroll
    for (int i = 0; i < 8; i++) {
        int m = m0 + ty * 8 + i;
        int s = m & 2047, bb = m >> 11;
        int t = dir ? (2047 - s) : s;
        float* o = g_xproj + ((((dir * SQ + t) * NB + bb) * NG) + n0 + tx * 8);
        float4 v0, v1;
        v0.x = acc[i][0] + bias[0]; v0.y = acc[i][1] + bias[1];
        v0.z = acc[i][2] + bias[2]; v0.w = acc[i][3] + bias[3];
        v1.x = acc[i][4] + bias[4]; v1.y = acc[i][5] + bias[5];
        v1.z = acc[i][6] + bias[6]; v1.w = acc[i][7] + bias[7];
        *(float4*)(o)     = v0;
        *(float4*)(o + 4) = v1;
    }
}

// ---------------- K2: dual-direction persistent BiLSTM ---------------------
// 64 CTAs; CTA r owns units [6r, 6r+6) for BOTH directions. Each step:
// compute fwd -> publish fwd -> compute bwd (hides fwd L2 propagation) ->
// publish bwd -> wait fwd (already visible) -> fetch h_f overlapped with
// bwd-flag polling -> fetch h_b. Exchange latency hidden behind compute.
__global__ void __launch_bounds__(256, 1) k_lstm(
    const float* __restrict__ Whhf, const float* __restrict__ Whhb,
    const int* __restrict__ utter)
{
    const int r  = blockIdx.x;           // 0..63
    const int j0 = r * 6;
    const int tid = threadIdx.x;
    const int wid = tid >> 5, lane = tid & 31;

    __shared__ __align__(16) float h_f[NB][HD];
    __shared__ __align__(16) float h_b[NB][HD];
    __shared__ float gate_f[24][NB];
    __shared__ float gate_b[24][NB];
    __shared__ float segmax_s[2][NB][33][6];

    for (int i = tid; i < NB * HD; i += 256) {
        (&h_f[0][0])[i] = 0.f;
        (&h_b[0][0])[i] = 0.f;
    }
    for (int i = tid; i < 2 * NB * 33 * 6; i += 256) (&segmax_s[0][0][0][0])[i] = 0.f;

    // warp wid owns rows 3*wid..3*wid+2 (row lr -> gate g=lr/6, unit jj=lr%6)
    unsigned long long wpf[3][6], wpb[3][6];
#pragma unroll
    for (int i = 0; i < 3; i++) {
        int lrw = wid * 3 + i;
        int g = lrw / 6, jj = lrw % 6;
        long roff = (long)(g * HD + j0 + jj) * HD;
#pragma unroll
        for (int q = 0; q < 3; q++) {
            ulonglong2 vf = *(const ulonglong2*)(Whhf + roff + q * 128 + lane * 4);
            ulonglong2 vb = *(const ulonglong2*)(Whhb + roff + q * 128 + lane * 4);
            wpf[i][q * 2 + 0] = vf.x; wpf[i][q * 2 + 1] = vf.y;
            wpb[i][q * 2 + 0] = vb.x; wpb[i][q * 2 + 1] = vb.y;
        }
    }

    const int jj_a = tid / 8, b_a = tid % 8;      // activation thread (tid<48)
    float cf = 0.f, cb = 0.f;
    unsigned* flagF = g_flag;                     // dir 0 lines
    unsigned* flagB = g_flag + 64 * 32;           // dir 1 lines
    float* hbF = g_hbuf;                          // [buf][b][j]
    float* hbB = g_hbuf + 2 * NB * HD;

    __syncthreads();

    for (int t = 0; t < SQ; t++) {
        // prefetch xproj (both dirs) + utterance ids (hidden under FMA)
        float xf0 = 0.f, xf1 = 0.f, xf2 = 0.f, xf3 = 0.f;
        float xb0 = 0.f, xb1 = 0.f, xb2 = 0.f, xb3 = 0.f;
        int uf = 0, ub = 0;
        if (tid < 48) {
            const float* xfp = g_xproj + (((long)t * NB + b_a) * NG) + j0 + jj_a;
            const float* xbp = g_xproj + (((long)(SQ + t) * NB + b_a) * NG) + j0 + jj_a;
            xf0 = xfp[0]; xf1 = xfp[HD]; xf2 = xfp[2 * HD]; xf3 = xfp[3 * HD];
            xb0 = xbp[0]; xb1 = xbp[HD]; xb2 = xbp[2 * HD]; xb3 = xbp[3 * HD];
            int u1 = utter[b_a * SQ + t];
            int u2 = utter[b_a * SQ + (SQ - 1 - t)];
            uf = u1 > 0 ? u1 : 0;
            ub = u2 > 0 ? u2 : 0;
        }

        // ---- fwd gate FMA: 3 rows x 8 batches, 6 f32x2 k-pairs per lane ----
        {
            unsigned long long p2[3][8];
#pragma unroll
            for (int i = 0; i < 3; i++)
#pragma unroll
                for (int b = 0; b < 8; b++) p2[i][b] = 0ull;
#pragma unroll
            for (int b = 0; b < 8; b++) {
                ulonglong2 h0 = *(const ulonglong2*)&h_f[b][lane * 4];
                ulonglong2 h1 = *(const ulonglong2*)&h_f[b][128 + lane * 4];
                ulonglong2 h2 = *(const ulonglong2*)&h_f[b][256 + lane * 4];
#pragma unroll
                for (int i = 0; i < 3; i++) {
                    unsigned long long s = p2[i][b];
                    s = fma2(wpf[i][0], h0.x, s);
                    s = fma2(wpf[i][1], h0.y, s);
                    s = fma2(wpf[i][2], h1.x, s);
                    s = fma2(wpf[i][3], h1.y, s);
                    s = fma2(wpf[i][4], h2.x, s);
                    s = fma2(wpf[i][5], h2.y, s);
                    p2[i][b] = s;
                }
            }
#pragma unroll
            for (int i = 0; i < 3; i++)
#pragma unroll
                for (int b = 0; b < 8; b++) {
                    float2 f = upk2(p2[i][b]);
                    float v = f.x + f.y;
                    v += __shfl_xor_sync(0xffffffffu, v, 16);
                    v += __shfl_xor_sync(0xffffffffu, v, 8);
                    v += __shfl_xor_sync(0xffffffffu, v, 4);
                    v += __shfl_xor_sync(0xffffffffu, v, 2);
                    v += __shfl_xor_sync(0xffffffffu, v, 1);
                    if (lane == 0) gate_f[wid * 3 + i][b] = v;
                }
        }
        __syncthreads();                                     // S1: gate_f ready

        // fwd activation + publish (warps 0-1 only; named barrier 1)
        if (tid < 48) {
            float vi = gate_f[jj_a][b_a]      + xf0;
            float vf = gate_f[6 + jj_a][b_a]  + xf1;
            float vg = gate_f[12 + jj_a][b_a] + xf2;
            float vo = gate_f[18 + jj_a][b_a] + xf3;
            float si = 1.f / (1.f + __expf(-vi));
            float sf = 1.f / (1.f + __expf(-vf));
            float so = 1.f / (1.f + __expf(-vo));
            float tg, tc;
            asm("tanh.approx.f32 %0, %1;" : "=f"(tg) : "f"(vg));
            cf = sf * cf + si * tg;
            asm("tanh.approx.f32 %0, %1;" : "=f"(tc) : "f"(cf));
            float h = so * tc;
            __stcg(hbF + (t & 1) * NB * HD + b_a * HD + j0 + jj_a, h);
            float* sm = &segmax_s[0][b_a][uf][jj_a];
            *sm = fmaxf(*sm, h);
        }
        if (tid < 64) {
            asm volatile("bar.sync 1, 64;" ::: "memory");
            if (tid == 0)
                asm volatile("st.release.gpu.global.u32 [%0], %1;"
                             :: "l"(flagF + r * 32), "r"((unsigned)(t + 1)) : "memory");
        }

        // ---- bwd gate FMA (covers fwd flag/data L2 propagation) ----
        {
            unsigned long long p2[3][8];
#pragma unroll
            for (int i = 0; i < 3; i++)
#pragma unroll
                for (int b = 0; b < 8; b++) p2[i][b] = 0ull;
#pragma unroll
            for (int b = 0; b < 8; b++) {
                ulonglong2 h0 = *(const ulonglong2*)&h_b[b][lane * 4];
                ulonglong2 h1 = *(const ulonglong2*)&h_b[b][128 + lane * 4];
                ulonglong2 h2 = *(const ulonglong2*)&h_b[b][256 + lane * 4];
#pragma unroll
                for (int i = 0; i < 3; i++) {
                    unsigned long long s = p2[i][b];
                    s = fma2(wpb[i][0], h0.x, s);
                    s = fma2(wpb[i][1], h0.y, s);
                    s = fma2(wpb[i][2], h1.x, s);
                    s = fma2(wpb[i][3], h1.y, s);
                    s = fma2(wpb[i][4], h2.x, s);
                    s = fma2(wpb[i][5], h2.y, s);
                    p2[i][b] = s;
                }
            }
#pragma unroll
            for (int i = 0; i < 3; i++)
#pragma unroll
                for (int b = 0; b < 8; b++) {
                    float2 f = upk2(p2[i][b]);
                    float v = f.x + f.y;
                    v += __shfl_xor_sync(0xffffffffu, v, 16);
                    v += __shfl_xor_sync(0xffffffffu, v, 8);
                    v += __shfl_xor_sync(0xffffffffu, v, 4);
                    v += __shfl_xor_sync(0xffffffffu, v, 2);
                    v += __shfl_xor_sync(0xffffffffu, v, 1);
                    if (lane == 0) gate_b[wid * 3 + i][b] = v;
                }
        }
        __syncthreads();                                     // S2: gate_b ready

        // bwd activation + publish
        if (tid < 48) {
            float vi = gate_b[jj_a][b_a]      + xb0;
            float vf = gate_b[6 + jj_a][b_a]  + xb1;
            float vg = gate_b[12 + jj_a][b_a] + xb2;
            float vo = gate_b[18 + jj_a][b_a] + xb3;
            float si = 1.f / (1.f + __expf(-vi));
            float sf = 1.f / (1.f + __expf(-vf));
            float so = 1.f / (1.f + __expf(-vo));
            float tg, tc;
            asm("tanh.approx.f32 %0, %1;" : "=f"(tg) : "f"(vg));
            cb = sf * cb + si * tg;
            asm("tanh.approx.f32 %0, %1;" : "=f"(tc) : "f"(cb));
            float h = so * tc;
            __stcg(hbB + (t & 1) * NB * HD + b_a * HD + j0 + jj_a, h);
            float* sm = &segmax_s[1][b_a][ub][jj_a];
            *sm = fmaxf(*sm, h);
        }
        if (tid < 64) {
            asm volatile("bar.sync 1, 64;" ::: "memory");
            if (tid == 0)
                asm volatile("st.release.gpu.global.u32 [%0], %1;"
                             :: "l"(flagB + r * 32), "r"((unsigned)(t + 1)) : "memory");
        }

        // ---- wait fwd flags (should be visible already) ----
        if (wid < 2) {
            unsigned tgt = (unsigned)(t + 1);
            const unsigned* fp = flagF + (wid * 32 + lane) * 32;
            unsigned v;
            do {
                asm volatile("ld.acquire.gpu.global.u32 %0, [%1];"
                             : "=r"(v) : "l"(fp) : "memory");
            } while (!__all_sync(0xffffffffu, v >= tgt));
        }
        __syncthreads();                                     // S3

        // ---- overlap: warps 0-1 poll bwd flags, warps 2-7 fetch h_f ----
        if (wid < 2) {
            unsigned tgt = (unsigned)(t + 1);
            const unsigned* fp = flagB + (wid * 32 + lane) * 32;
            unsigned v;
            do {
                asm volatile("ld.acquire.gpu.global.u32 %0, [%1];"
                             : "=r"(v) : "l"(fp) : "memory");
            } while (!__all_sync(0xffffffffu, v >= tgt));
        } else {
            const float4* src = (const float4*)(hbF + (t & 1) * NB * HD);
            float4* dst = (float4*)(&h_f[0][0]);
            int i = tid - 64;
            dst[i]       = __ldcg(src + i);
            dst[i + 192] = __ldcg(src + i + 192);
            dst[i + 384] = __ldcg(src + i + 384);
            dst[i + 576] = __ldcg(src + i + 576);
        }
        __syncthreads();                                     // S4

        // ---- fetch h_b (all threads) ----
        {
            const float4* src = (const float4*)(hbB + (t & 1) * NB * HD);
            float4* dst = (float4*)(&h_b[0][0]);
            dst[tid]       = __ldcg(src + tid);
            dst[tid + 256] = __ldcg(src + tid + 256);
            dst[tid + 512] = __ldcg(src + tid + 512);
        }
        __syncthreads();                                     // S5
    }

    // emit mp: fwd -> [0:384), bwd -> [384:768)
    if (tid < 48) {
        for (int u = 1; u <= NU; u++) {
            g_mp[(b_a * NU + (u - 1)) * HDIM + j0 + jj_a] =
                segmax_s[0][b_a][u][jj_a];
            g_mp[(b_a * NU + (u - 1)) * HDIM + HD + j0 + jj_a] =
                segmax_s[1][b_a][u][jj_a];
        }
    }
}

// ---------------- K3: topic softmax routing ---------------------------------
__global__ void __launch_bounds__(256) k_route(
    const float* __restrict__ tw, const float* __restrict__ tb,
    const float* __restrict__ table)
{
    const int b = blockIdx.x >> 5;
    const int u = blockIdx.x & 31;
    __shared__ float mp_s[768];
    __shared__ float lp_s[4][64];
    __shared__ float l_s[64], e_s[64];
    const int tid = threadIdx.x;
    const float* mpr = g_mp + (b * NU + u) * HDIM;
    for (int i = tid; i < 192; i += 256)
        ((float4*)mp_s)[i] = ((const float4*)mpr)[i];
    __syncthreads();
    {
        const int topic = tid & 63, slice = tid >> 6;
        float acc = 0.f;
        const float* wr = tw + topic * 768 + slice * 192;
        const float* ms = mp_s + slice * 192;
        for (int k = 0; k < 192; k += 4) {
            float4 wv = *(const float4*)(wr + k);
            acc = fmaf(wv.x, ms[k], acc);
            acc = fmaf(wv.y, ms[k + 1], acc);
            acc = fmaf(wv.z, ms[k + 2], acc);
            acc = fmaf(wv.w, ms[k + 3], acc);
        }
        lp_s[slice][topic] = acc;
    }
    __syncthreads();
    if (tid < 64)
        l_s[tid] = lp_s[0][tid] + lp_s[1][tid] + lp_s[2][tid] + lp_s[3][tid] + tb[tid];
    __syncthreads();
    if (tid < 64) {
        float mx = -1e30f;
        for (int i = 0; i < 64; i++) mx = fmaxf(mx, l_s[i]);
        e_s[tid] = expf(l_s[tid] - mx);
    }
    __syncthreads();
    float ssum = 0.f;
    for (int i = 0; i < 64; i++) ssum += e_s[i];
    float inv = 1.f / ssum;
    for (int h = tid; h < 768; h += 256) {
        float acc = 0.f;
        for (int tt = 0; tt < 64; tt++)
            acc = fmaf(e_s[tt], table[tt * 768 + h], acc);
        g_emb[(b * NU + u) * HDIM + h] = acc * inv;
    }
}

// ---------------- K4: scatter back to token positions -----------------------
__global__ void __launch_bounds__(256) k_scatter(
    const int* __restrict__ utter, float* __restrict__ out)
{
    int v = blockIdx.x * 256 + threadIdx.x;
    int m = v / 192;
    int h4 = v - m * 192;
    int u = __ldg(utter + m);
    float4 o = make_float4(0.f, 0.f, 0.f, 0.f);
    if (u != 0) {
        int idx = u > 0 ? u - 1 : -u - 1;
        if (idx > 31) idx = 31;
        int bb = m >> 11;
        float4 gv = *(const float4*)(g_emb + (bb * NU + idx) * HDIM + h4 * 4);
        float sc = u > 0 ? 1.f : 2.f;
        o.x = gv.x * sc; o.y = gv.y * sc; o.z = gv.z * sc; o.w = gv.w * sc;
    }
    ((float4*)out)[v] = o;
}

// ---------------- launch -----------------------------------------------------
extern "C" void kernel_launch(void* const* d_in, const int* in_sizes, int n_in,
                              void* d_out, int out_size)
{
    const float* X     = (const float*)d_in[0];
    const float* Wihf  = (const float*)d_in[1];
    const float* Whhf  = (const float*)d_in[2];
    const float* bihf  = (const float*)d_in[3];
    const float* bhhf  = (const float*)d_in[4];
    const float* Wihb  = (const float*)d_in[5];
    const float* Whhb  = (const float*)d_in[6];
    const float* bihb  = (const float*)d_in[7];
    const float* bhhb  = (const float*)d_in[8];
    const float* tw    = (const float*)d_in[9];
    const float* tb    = (const float*)d_in[10];
    const float* table = (const float*)d_in[11];
    const int*   utter = (const int*)d_in[12];

    // 1 pad: ncu capture (launch #4) lands on k_lstm
    k_pad<<<1, 32>>>();
    k_reset<<<16, 256>>>();
    k_gemm<<<dim3(12, 128, 2), 256>>>(X, Wihf, Wihb, bihf, bhhf, bihb, bhhb);
    k_lstm<<<64, 256>>>(Whhf, Whhb, utter);
    k_route<<<256, 256>>>(tw, tb, table);
    k_scatter<<<12288, 256>>>(utter, (float*)d_out);
}

// round 7
// speedup vs baseline: 1.1460x; 1.1460x over previous
#include <cuda_runtime.h>
#include <math.h>

#define SQ 2048
#define NB 8
#define HDIM 768
#define HD 384
#define NG 1536
#define NT 64
#define NU 32

// ---------------- device scratch (static, no runtime alloc) ----------------
__device__ float    g_xproj[2u * SQ * NB * NG];   // [dir][t][b][gate_row]  ~201 MB
__device__ float    g_hbuf [2 * 2 * NB * HD];     // [dir][buf][b][j]
__device__ unsigned g_flag [2 * 64 * 32];         // one 128B line per (dir, cta)
__device__ float    g_mp   [NB * NU * HDIM];      // [b][u][h] pooled features
__device__ float    g_emb  [NB * NU * HDIM];      // [b][u][h] routed embeddings

// ---------------- f32x2 packed-FMA helper (operands loaded pre-paired) -----
__device__ __forceinline__ unsigned long long fma2(
    unsigned long long a, unsigned long long b, unsigned long long c) {
    unsigned long long d;
    asm("fma.rn.f32x2 %0, %1, %2, %3;" : "=l"(d) : "l"(a), "l"(b), "l"(c));
    return d;
}
__device__ __forceinline__ float2 upk2(unsigned long long v) {
    float2 f;
    asm("mov.b64 {%0,%1}, %2;" : "=f"(f.x), "=f"(f.y) : "l"(v));
    return f;
}

// ---------------- pad kernel: 2 pads put k_gemm at launch #4 (ncu) ---------
__global__ void k_pad() {}

// ---------------- flag reset (graph replays must be deterministic) ---------
__global__ void k_reset()
{
    int i = blockIdx.x * 256 + threadIdx.x;
    if (i < 2 * 64 * 32) g_flag[i] = 0u;
}

// ---------------- K1: input projection GEMM (both directions) --------------
// (R1 version — known good)
__global__ void __launch_bounds__(256) k_gemm(
    const float* __restrict__ X,
    const float* __restrict__ Wf, const float* __restrict__ Wb,
    const float* __restrict__ bihf, const float* __restrict__ bhhf,
    const float* __restrict__ bihb, const float* __restrict__ bhhb)
{
    const int dir = blockIdx.z;
    const float* W = dir ? Wb : Wf;
    const int n0 = blockIdx.x * 128;
    const int m0 = blockIdx.y * 128;

    __shared__ float As[8][128];
    __shared__ float Bs[8][128];

    const int tid = threadIdx.x;
    const int lr = tid >> 1, lh = tid & 1;
    const int tx = tid & 15, ty = tid >> 4;

    float acc[8][8];
#pragma unroll
    for (int i = 0; i < 8; i++)
#pragma unroll
        for (int j = 0; j < 8; j++) acc[i][j] = 0.f;

    const float* xptr = X + (m0 + lr) * 768 + lh * 4;
    const float* wptr = W + (n0 + lr) * 768 + lh * 4;

    for (int kt = 0; kt < 768; kt += 8) {
        float4 av = *(const float4*)(xptr + kt);
        float4 bv = *(const float4*)(wptr + kt);
        __syncthreads();
        As[lh * 4 + 0][lr] = av.x; As[lh * 4 + 1][lr] = av.y;
        As[lh * 4 + 2][lr] = av.z; As[lh * 4 + 3][lr] = av.w;
        Bs[lh * 4 + 0][lr] = bv.x; Bs[lh * 4 + 1][lr] = bv.y;
        Bs[lh * 4 + 2][lr] = bv.z; Bs[lh * 4 + 3][lr] = bv.w;
        __syncthreads();
#pragma unroll
        for (int k = 0; k < 8; k++) {
            float a[8], b[8];
            *(float4*)(a)     = *(const float4*)&As[k][ty * 8];
            *(float4*)(a + 4) = *(const float4*)&As[k][ty * 8 + 4];
            *(float4*)(b)     = *(const float4*)&Bs[k][tx * 8];
            *(float4*)(b + 4) = *(const float4*)&Bs[k][tx * 8 + 4];
#pragma unroll
            for (int i = 0; i < 8; i++)
#pragma unroll
                for (int j = 0; j < 8; j++)
                    acc[i][j] = fmaf(a[i], b[j], acc[i][j]);
        }
    }

    const float* bi = dir ? bihb : bihf;
    const float* bh = dir ? bhhb : bhhf;
    float bias[8];
#pragma unroll
    for (int j = 0; j < 8; j++) {
        int n = n0 + tx * 8 + j;
        bias[j] = bi[n] + bh[n];
    }
#pragma unroll
    for (int i = 0; i < 8; i++) {
        int m = m0 + ty * 8 + i;
        int s = m & 2047, bb = m >> 11;
        int t = dir ? (2047 - s) : s;
        float* o = g_xproj + ((((dir * SQ + t) * NB + bb) * NG) + n0 + tx * 8);
        float4 v0, v1;
        v0.x = acc[i][0] + bias[0]; v0.y = acc[i][1] + bias[1];
        v0.z = acc[i][2] + bias[2]; v0.w = acc[i][3] + bias[3];
        v1.x = acc[i][4] + bias[4]; v1.y = acc[i][5] + bias[5];
        v1.z = acc[i][6] + bias[6]; v1.w = acc[i][7] + bias[7];
        *(float4*)(o)     = v0;
        *(float4*)(o + 4) = v1;
    }
}

// ---------------- K2: persistent BiLSTM recurrence + fused segment max -----
// R4 structure (barrier/fetch/activation identical). Compute remap: 8 warps =
// 4 gate-groups x 2 batch-halves; warp (g, bg) computes gate g, 6 units,
// batches [4bg, 4bg+4). Each warp reads only 4 batches of h -> smem crossbar
// traffic halves (98KB -> 49KB per step per SM), dropping below FFMA2 issue.
// k-pairs at lane*2 + 64q give aligned 8B f32x2 operands, conflict-free.
__global__ void __launch_bounds__(256, 1) k_lstm(
    const float* __restrict__ Whhf, const float* __restrict__ Whhb,
    const int* __restrict__ utter)
{
    const int dir = blockIdx.x >> 6;
    const int r   = blockIdx.x & 63;
    const int j0  = r * 6;
    const float* Whh = dir ? Whhb : Whhf;
    const int tid = threadIdx.x;
    const int wid = tid >> 5, lane = tid & 31;
    const int gate = wid >> 1;       // 0..3
    const int bg   = wid & 1;        // batches [4bg, 4bg+4)

    __shared__ __align__(16) float h_s[NB][HD];   // current hidden, all batches
    __shared__ float gate_s[24][NB];              // row = gate*6 + unit
    __shared__ float segmax_s[NB][33][6];         // fused per-utterance max

    for (int i = tid; i < NB * HD; i += 256) (&h_s[0][0])[i] = 0.f;
    for (int i = tid; i < NB * 33 * 6; i += 256) (&segmax_s[0][0][0])[i] = 0.f;

    // weights: wp[i][q] = Whh[(gate*HD + j0 + i)*HD + lane*2 + 64q] (f32x2)
    unsigned long long wp[6][6];
#pragma unroll
    for (int i = 0; i < 6; i++) {
        const float* wr = Whh + (long)(gate * HD + j0 + i) * HD + lane * 2;
#pragma unroll
        for (int q = 0; q < 6; q++)
            wp[i][q] = *(const unsigned long long*)(wr + 64 * q);
    }

    const int jj_a = tid / 8, b_a = tid % 8;      // activation thread (tid<48)
    float c_state = 0.f;
    unsigned* flags = g_flag + dir * 64 * 32;     // line r at flags + r*32
    float* hbase = g_hbuf + dir * 2 * NB * HD;

    __syncthreads();

    for (int t = 0; t < SQ; t++) {
        // prefetch xproj + utterance id (hidden under the FMA phase)
        float xp0 = 0.f, xp1 = 0.f, xp2 = 0.f, xp3 = 0.f;
        int useg = 0;
        if (tid < 48) {
            int pos = dir ? (SQ - 1 - t) : t;
            const float* xb = g_xproj + ((((dir * SQ + t) * NB + b_a) * NG) + j0 + jj_a);
            xp0 = xb[0]; xp1 = xb[HD]; xp2 = xb[2 * HD]; xp3 = xb[3 * HD];
            int u = utter[b_a * SQ + pos];
            useg = u > 0 ? u : 0;
        }

        // gate partials: 6 units x 4 batches, 6 f32x2 k-pairs per lane
        unsigned long long p2[6][4];
#pragma unroll
        for (int i = 0; i < 6; i++)
#pragma unroll
            for (int b = 0; b < 4; b++) p2[i][b] = 0ull;
#pragma unroll
        for (int q = 0; q < 6; q++) {
            const int k = lane * 2 + 64 * q;
            unsigned long long hq[4];
#pragma unroll
            for (int b = 0; b < 4; b++)
                hq[b] = *(const unsigned long long*)&h_s[bg * 4 + b][k];
#pragma unroll
            for (int i = 0; i < 6; i++) {
                unsigned long long wv = wp[i][q];
                p2[i][0] = fma2(wv, hq[0], p2[i][0]);
                p2[i][1] = fma2(wv, hq[1], p2[i][1]);
                p2[i][2] = fma2(wv, hq[2], p2[i][2]);
                p2[i][3] = fma2(wv, hq[3], p2[i][3]);
            }
        }
#pragma unroll
        for (int i = 0; i < 6; i++)
#pragma unroll
            for (int b = 0; b < 4; b++) {
                float2 f = upk2(p2[i][b]);
                float v = f.x + f.y;
                v += __shfl_xor_sync(0xffffffffu, v, 16);
                v += __shfl_xor_sync(0xffffffffu, v, 8);
                v += __shfl_xor_sync(0xffffffffu, v, 4);
                v += __shfl_xor_sync(0xffffffffu, v, 2);
                v += __shfl_xor_sync(0xffffffffu, v, 1);
                if (lane == 0) gate_s[gate * 6 + i][bg * 4 + b] = v;
            }
        __syncthreads();

        // activation + publish + fused segment max (MUFU approx)
        if (tid < 48) {
            float vi = gate_s[jj_a][b_a]      + xp0;
            float vf = gate_s[6 + jj_a][b_a]  + xp1;
            float vg = gate_s[12 + jj_a][b_a] + xp2;
            float vo = gate_s[18 + jj_a][b_a] + xp3;
            float si = 1.f / (1.f + __expf(-vi));
            float sf = 1.f / (1.f + __expf(-vf));
            float so = 1.f / (1.f + __expf(-vo));
            float tg, tc;
            asm("tanh.approx.f32 %0, %1;" : "=f"(tg) : "f"(vg));
            c_state = sf * c_state + si * tg;
            asm("tanh.approx.f32 %0, %1;" : "=f"(tc) : "f"(c_state));
            float h = so * tc;
            __stcg(hbase + (t & 1) * NB * HD + b_a * HD + j0 + jj_a, h);
            float* sm = &segmax_s[b_a][useg][jj_a];
            *sm = fmaxf(*sm, h);
        }
        __syncthreads();

        // inter-CTA barrier: release-store own line, poll one line per lane
        if (tid == 0) {
            asm volatile("st.release.gpu.global.u32 [%0], %1;"
                         :: "l"(flags + r * 32), "r"((unsigned)(t + 1)) : "memory");
        }
        if (wid < 2) {
            unsigned tgt = (unsigned)(t + 1);
            const unsigned* fp = flags + (wid * 32 + lane) * 32;
            unsigned v;
            do {
                asm volatile("ld.acquire.gpu.global.u32 %0, [%1];"
                             : "=r"(v) : "l"(fp) : "memory");
            } while (!__all_sync(0xffffffffu, v >= tgt));
        }
        __syncthreads();

        // pull the full broadcast hidden state (L2, bypass L1)
        {
            const float4* src = (const float4*)(hbase + (t & 1) * NB * HD);
            float4* dst = (float4*)(&h_s[0][0]);
            for (int i = tid; i < NB * HD / 4; i += 256)
                dst[i] = __ldcg(src + i);
        }
        __syncthreads();
    }

    // emit mp[b][u][dir*384 + j] = max(segmax, 0)  (accumulator init was 0)
    if (tid < 48) {
        for (int u = 1; u <= NU; u++)
            g_mp[(b_a * NU + (u - 1)) * HDIM + dir * HD + j0 + jj_a] =
                segmax_s[b_a][u][jj_a];
    }
}

// ---------------- K3: topic softmax routing ---------------------------------
__global__ void __launch_bounds__(256) k_route(
    const float* __restrict__ tw, const float* __restrict__ tb,
    const float* __restrict__ table)
{
    const int b = blockIdx.x >> 5;
    const int u = blockIdx.x & 31;
    __shared__ float mp_s[768];
    __shared__ float lp_s[4][64];
    __shared__ float l_s[64], e_s[64];
    const int tid = threadIdx.x;
    const float* mpr = g_mp + (b * NU + u) * HDIM;
    for (int i = tid; i < 192; i += 256)
        ((float4*)mp_s)[i] = ((const float4*)mpr)[i];
    __syncthreads();
    {
        const int topic = tid & 63, slice = tid >> 6;
        float acc = 0.f;
        const float* wr = tw + topic * 768 + slice * 192;
        const float* ms = mp_s + slice * 192;
        for (int k = 0; k < 192; k += 4) {
            float4 wv = *(const float4*)(wr + k);
            acc = fmaf(wv.x, ms[k], acc);
            acc = fmaf(wv.y, ms[k + 1], acc);
            acc = fmaf(wv.z, ms[k + 2], acc);
            acc = fmaf(wv.w, ms[k + 3], acc);
        }
        lp_s[slice][topic] = acc;
    }
    __syncthreads();
    if (tid < 64)
        l_s[tid] = lp_s[0][tid] + lp_s[1][tid] + lp_s[2][tid] + lp_s[3][tid] + tb[tid];
    __syncthreads();
    if (tid < 64) {
        float mx = -1e30f;
        for (int i = 0; i < 64; i++) mx = fmaxf(mx, l_s[i]);
        e_s[tid] = expf(l_s[tid] - mx);
    }
    __syncthreads();
    float ssum = 0.f;
    for (int i = 0; i < 64; i++) ssum += e_s[i];
    float inv = 1.f / ssum;
    for (int h = tid; h < 768; h += 256) {
        float acc = 0.f;
        for (int tt = 0; tt < 64; tt++)
            acc = fmaf(e_s[tt], table[tt * 768 + h], acc);
        g_emb[(b * NU + u) * HDIM + h] = acc * inv;
    }
}

// ---------------- K4: scatter back to token positions -----------------------
__global__ void __launch_bounds__(256) k_scatter(
    const int* __restrict__ utter, float* __restrict__ out)
{
    int v = blockIdx.x * 256 + threadIdx.x;
    int m = v / 192;
    int h4 = v - m * 192;
    int u = __ldg(utter + m);
    float4 o = make_float4(0.f, 0.f, 0.f, 0.f);
    if (u != 0) {
        int idx = u > 0 ? u - 1 : -u - 1;
        if (idx > 31) idx = 31;
        int bb = m >> 11;
        float4 gv = *(const float4*)(g_emb + (bb * NU + idx) * HDIM + h4 * 4);
        float sc = u > 0 ? 1.f : 2.f;
        o.x = gv.x * sc; o.y = gv.y * sc; o.z = gv.z * sc; o.w = gv.w * sc;
    }
    ((float4*)out)[v] = o;
}

// ---------------- launch -----------------------------------------------------
extern "C" void kernel_launch(void* const* d_in, const int* in_sizes, int n_in,
                              void* d_out, int out_size)
{
    const float* X     = (const float*)d_in[0];
    const float* Wihf  = (const float*)d_in[1];
    const float* Whhf  = (const float*)d_in[2];
    const float* bihf  = (const float*)d_in[3];
    const float* bhhf  = (const float*)d_in[4];
    const float* Wihb  = (const float*)d_in[5];
    const float* Whhb  = (const float*)d_in[6];
    const float* bihb  = (const float*)d_in[7];
    const float* bhhb  = (const float*)d_in[8];
    const float* tw    = (const float*)d_in[9];
    const float* tb    = (const float*)d_in[10];
    const float* table = (const float*)d_in[11];
    const int*   utter = (const int*)d_in[12];

    // 2 pads: ncu capture (launch #4) lands on k_gemm
    k_pad<<<1, 32>>>();
    k_pad<<<1, 32>>>();
    k_reset<<<16, 256>>>();
    k_gemm<<<dim3(12, 128, 2), 256>>>(X, Wihf, Wihb, bihf, bhhf, bihb, bhhb);
    k_lstm<<<128, 256>>>(Whhf, Whhb, utter);
    k_route<<<256, 256>>>(tw, tb, table);
    k_scatter<<<12288, 256>>>(utter, (float*)d_out);
}

// round 8
// speedup vs baseline: 1.3409x; 1.1700x over previous
#include <cuda_runtime.h>
#include <math.h>

#define SQ 2048
#define NB 8
#define HDIM 768
#define HD 384
#define NG 1536
#define NT 64
#define NU 32

// ---------------- device scratch (static, no runtime alloc) ----------------
__device__ float    g_xproj[2u * SQ * NB * NG];   // [dir][t][b][gate_row]  ~201 MB
__device__ float    g_hbuf [8 * 2 * 2 * HD];      // [group][buf][b2][j]
__device__ unsigned g_flag [128 * 32];            // one 128B line per CTA
__device__ float    g_mp   [NB * NU * HDIM];      // [b][u][h] pooled features
__device__ float    g_emb  [NB * NU * HDIM];      // [b][u][h] routed embeddings

// ---------------- f32x2 packed-FMA helper (operands loaded pre-paired) -----
__device__ __forceinline__ unsigned long long fma2(
    unsigned long long a, unsigned long long b, unsigned long long c) {
    unsigned long long d;
    asm("fma.rn.f32x2 %0, %1, %2, %3;" : "=l"(d) : "l"(a), "l"(b), "l"(c));
    return d;
}
__device__ __forceinline__ float2 upk2(unsigned long long v) {
    float2 f;
    asm("mov.b64 {%0,%1}, %2;" : "=f"(f.x), "=f"(f.y) : "l"(v));
    return f;
}

// ---------------- pad kernel: 1 pad puts k_lstm at launch #4 (ncu) ---------
__global__ void k_pad() {}

// ---------------- flag reset (graph replays must be deterministic) ---------
__global__ void k_reset()
{
    int i = blockIdx.x * 256 + threadIdx.x;
    if (i < 128 * 32) g_flag[i] = 0u;
}

// ---------------- K1: input projection GEMM (both directions) --------------
// (R1 version — known good)
__global__ void __launch_bounds__(256) k_gemm(
    const float* __restrict__ X,
    const float* __restrict__ Wf, const float* __restrict__ Wb,
    const float* __restrict__ bihf, const float* __restrict__ bhhf,
    const float* __restrict__ bihb, const float* __restrict__ bhhb)
{
    const int dir = blockIdx.z;
    const float* W = dir ? Wb : Wf;
    const int n0 = blockIdx.x * 128;
    const int m0 = blockIdx.y * 128;

    __shared__ float As[8][128];
    __shared__ float Bs[8][128];

    const int tid = threadIdx.x;
    const int lr = tid >> 1, lh = tid & 1;
    const int tx = tid & 15, ty = tid >> 4;

    float acc[8][8];
#pragma unroll
    for (int i = 0; i < 8; i++)
#pragma unroll
        for (int j = 0; j < 8; j++) acc[i][j] = 0.f;

    const float* xptr = X + (m0 + lr) * 768 + lh * 4;
    const float* wptr = W + (n0 + lr) * 768 + lh * 4;

    for (int kt = 0; kt < 768; kt += 8) {
        float4 av = *(const float4*)(xptr + kt);
        float4 bv = *(const float4*)(wptr + kt);
        __syncthreads();
        As[lh * 4 + 0][lr] = av.x; As[lh * 4 + 1][lr] = av.y;
        As[lh * 4 + 2][lr] = av.z; As[lh * 4 + 3][lr] = av.w;
        Bs[lh * 4 + 0][lr] = bv.x; Bs[lh * 4 + 1][lr] = bv.y;
        Bs[lh * 4 + 2][lr] = bv.z; Bs[lh * 4 + 3][lr] = bv.w;
        __syncthreads();
#pragma unroll
        for (int k = 0; k < 8; k++) {
            float a[8], b[8];
            *(float4*)(a)     = *(const float4*)&As[k][ty * 8];
            *(float4*)(a + 4) = *(const float4*)&As[k][ty * 8 + 4];
            *(float4*)(b)     = *(const float4*)&Bs[k][tx * 8];
            *(float4*)(b + 4) = *(const float4*)&Bs[k][tx * 8 + 4];
#pragma unroll
            for (int i = 0; i < 8; i++)
#pragma unroll
                for (int j = 0; j < 8; j++)
                    acc[i][j] = fmaf(a[i], b[j], acc[i][j]);
        }
    }

    const float* bi = dir ? bihb : bihf;
    const float* bh = dir ? bhhb : bhhf;
    float bias[8];
#pragma unroll
    for (int j = 0; j < 8; j++) {
        int n = n0 + tx * 8 + j;
        bias[j] = bi[n] + bh[n];
    }
#pragma unroll
    for (int i = 0; i < 8; i++) {
        int m = m0 + ty * 8 + i;
        int s = m & 2047, bb = m >> 11;
        int t = dir ? (2047 - s) : s;
        float* o = g_xproj + ((((dir * SQ + t) * NB + bb) * NG) + n0 + tx * 8);
        float4 v0, v1;
        v0.x = acc[i][0] + bias[0]; v0.y = acc[i][1] + bias[1];
        v0.z = acc[i][2] + bias[2]; v0.w = acc[i][3] + bias[3];
        v1.x = acc[i][4] + bias[4]; v1.y = acc[i][5] + bias[5];
        v1.z = acc[i][6] + bias[6]; v1.w = acc[i][7] + bias[7];
        *(float4*)(o)     = v0;
        *(float4*)(o + 4) = v1;
    }
}

// ---------------- K2: group-decomposed persistent BiLSTM -------------------
// 8 independent groups = (dir, batch-pair), 16 CTAs each. Group runs its own
// 2048-step recurrence over 2 batches: 16-flag barrier domain, 3KB exchange.
// CTA c owns units [24c, 24c+24), all 4 gates, both batches; weights live in
// registers (144/thread as f32x2). Warp (g2 = wid>>1, half = wid&1) computes
// gate g2, units [24c+12*half, +12), lane covers k pairs (lane*2 + 64q).
__global__ void __launch_bounds__(256, 1) k_lstm(
    const float* __restrict__ Whhf, const float* __restrict__ Whhb,
    const int* __restrict__ utter)
{
    const int grp = blockIdx.x >> 4;      // 0..7
    const int c   = blockIdx.x & 15;      // 0..15
    const int dir = grp >> 2;
    const int bp  = grp & 3;              // batches 2bp, 2bp+1
    const int j0  = c * 24;
    const float* Whh = dir ? Whhb : Whhf;
    const int tid = threadIdx.x;
    const int wid = tid >> 5, lane = tid & 31;
    const int g2   = wid >> 1;            // gate 0..3
    const int half = wid & 1;             // unit half
    const int jw   = j0 + half * 12;      // warp's first unit

    __shared__ __align__(16) float h_s[2][HD];   // 2 batches x 384
    __shared__ float gate_s[4][24][2];           // [gate][jj][b2]
    __shared__ float segmax_s[2][33][24];        // [b2][useg][jj]

    for (int i = tid; i < 2 * HD; i += 256) (&h_s[0][0])[i] = 0.f;
    for (int i = tid; i < 2 * 33 * 24; i += 256) (&segmax_s[0][0][0])[i] = 0.f;

    // weights: wp[i][q] = Whh[(g2*HD + jw + i)*HD + lane*2 + 64q]  (f32x2)
    unsigned long long wp[12][6];
#pragma unroll
    for (int i = 0; i < 12; i++) {
        const float* wr = Whh + (long)(g2 * HD + jw + i) * HD + lane * 2;
#pragma unroll
        for (int q = 0; q < 6; q++)
            wp[i][q] = *(const unsigned long long*)(wr + 64 * q);
    }

    // activation thread mapping (tid < 48): unit jj_a, batch-slot b2_a
    const int jj_a = tid >> 1, b2_a = tid & 1;
    const int batch_a = bp * 2 + b2_a;
    float c_state = 0.f;
    unsigned* flags = g_flag + grp * 16 * 32;     // line c at flags + c*32
    float* hbase = g_hbuf + grp * 2 * 2 * HD;     // [buf][b2][j]

    __syncthreads();

    for (int t = 0; t < SQ; t++) {
        // prefetch xproj + utterance id (hidden under the FMA phase)
        float xp0 = 0.f, xp1 = 0.f, xp2 = 0.f, xp3 = 0.f;
        int useg = 0;
        if (tid < 48) {
            int pos = dir ? (SQ - 1 - t) : t;
            const float* xb = g_xproj +
                ((((long)dir * SQ + t) * NB + batch_a) * NG) + j0 + jj_a;
            xp0 = xb[0]; xp1 = xb[HD]; xp2 = xb[2 * HD]; xp3 = xb[3 * HD];
            int u = utter[batch_a * SQ + pos];
            useg = u > 0 ? u : 0;
        }

        // gate partials: 12 rows, batches sequential (shared weights)
#pragma unroll
        for (int b2 = 0; b2 < 2; b2++) {
            unsigned long long p2[12];
#pragma unroll
            for (int i = 0; i < 12; i++) p2[i] = 0ull;
#pragma unroll
            for (int q = 0; q < 6; q++) {
                unsigned long long hq =
                    *(const unsigned long long*)&h_s[b2][lane * 2 + 64 * q];
#pragma unroll
                for (int i = 0; i < 12; i++)
                    p2[i] = fma2(wp[i][q], hq, p2[i]);
            }
#pragma unroll
            for (int i = 0; i < 12; i++) {
                float2 f = upk2(p2[i]);
                float v = f.x + f.y;
                v += __shfl_xor_sync(0xffffffffu, v, 16);
                v += __shfl_xor_sync(0xffffffffu, v, 8);
                v += __shfl_xor_sync(0xffffffffu, v, 4);
                v += __shfl_xor_sync(0xffffffffu, v, 2);
                v += __shfl_xor_sync(0xffffffffu, v, 1);
                if (lane == 0) gate_s[g2][half * 12 + i][b2] = v;
            }
        }
        __syncthreads();

        // activation + publish + fused segment max (MUFU approx)
        if (tid < 48) {
            float vi = gate_s[0][jj_a][b2_a] + xp0;
            float vf = gate_s[1][jj_a][b2_a] + xp1;
            float vg = gate_s[2][jj_a][b2_a] + xp2;
            float vo = gate_s[3][jj_a][b2_a] + xp3;
            float si = 1.f / (1.f + __expf(-vi));
            float sf = 1.f / (1.f + __expf(-vf));
            float so = 1.f / (1.f + __expf(-vo));
            float tg, tc;
            asm("tanh.approx.f32 %0, %1;" : "=f"(tg) : "f"(vg));
            c_state = sf * c_state + si * tg;
            asm("tanh.approx.f32 %0, %1;" : "=f"(tc) : "f"(c_state));
            float h = so * tc;
            __stcg(hbase + (t & 1) * 2 * HD + b2_a * HD + j0 + jj_a, h);
            float* sm = &segmax_s[b2_a][useg][jj_a];
            *sm = fmaxf(*sm, h);
        }
        __syncthreads();

        // group barrier: release-store own line, warp 0 polls 16 lines
        if (tid == 0) {
            asm volatile("st.release.gpu.global.u32 [%0], %1;"
                         :: "l"(flags + c * 32), "r"((unsigned)(t + 1)) : "memory");
        }
        if (wid == 0) {
            unsigned tgt = (unsigned)(t + 1);
            const unsigned* fp = flags + lane * 32;
            bool ok;
            do {
                unsigned v = tgt;
                if (lane < 16)
                    asm volatile("ld.acquire.gpu.global.u32 %0, [%1];"
                                 : "=r"(v) : "l"(fp) : "memory");
                ok = __all_sync(0xffffffffu, v >= tgt);
            } while (!ok);
        }
        __syncthreads();

        // pull the group's hidden state (768 floats, 1 float4 per thread)
        if (tid < 192) {
            const float4* src = (const float4*)(hbase + (t & 1) * 2 * HD);
            ((float4*)(&h_s[0][0]))[tid] = __ldcg(src + tid);
        }
        __syncthreads();
    }

    // emit mp[b][u][dir*384 + j] = max(segmax, 0)  (accumulator init was 0)
    if (tid < 48) {
        for (int u = 1; u <= NU; u++)
            g_mp[(batch_a * NU + (u - 1)) * HDIM + dir * HD + j0 + jj_a] =
                segmax_s[b2_a][u][jj_a];
    }
}

// ---------------- K3: topic softmax routing ---------------------------------
__global__ void __launch_bounds__(256) k_route(
    const float* __restrict__ tw, const float* __restrict__ tb,
    const float* __restrict__ table)
{
    const int b = blockIdx.x >> 5;
    const int u = blockIdx.x & 31;
    __shared__ float mp_s[768];
    __shared__ float lp_s[4][64];
    __shared__ float l_s[64], e_s[64];
    const int tid = threadIdx.x;
    const float* mpr = g_mp + (b * NU + u) * HDIM;
    for (int i = tid; i < 192; i += 256)
        ((float4*)mp_s)[i] = ((const float4*)mpr)[i];
    __syncthreads();
    {
        const int topic = tid & 63, slice = tid >> 6;
        float acc = 0.f;
        const float* wr = tw + topic * 768 + slice * 192;
        const float* ms = mp_s + slice * 192;
        for (int k = 0; k < 192; k += 4) {
            float4 wv = *(const float4*)(wr + k);
            acc = fmaf(wv.x, ms[k], acc);
            acc = fmaf(wv.y, ms[k + 1], acc);
            acc = fmaf(wv.z, ms[k + 2], acc);
            acc = fmaf(wv.w, ms[k + 3], acc);
        }
        lp_s[slice][topic] = acc;
    }
    __syncthreads();
    if (tid < 64)
        l_s[tid] = lp_s[0][tid] + lp_s[1][tid] + lp_s[2][tid] + lp_s[3][tid] + tb[tid];
    __syncthreads();
    if (tid < 64) {
        float mx = -1e30f;
        for (int i = 0; i < 64; i++) mx = fmaxf(mx, l_s[i]);
        e_s[tid] = expf(l_s[tid] - mx);
    }
    __syncthreads();
    float ssum = 0.f;
    for (int i = 0; i < 64; i++) ssum += e_s[i];
    float inv = 1.f / ssum;
    for (int h = tid; h < 768; h += 256) {
        float acc = 0.f;
        for (int tt = 0; tt < 64; tt++)
            acc = fmaf(e_s[tt], table[tt * 768 + h], acc);
        g_emb[(b * NU + u) * HDIM + h] = acc * inv;
    }
}

// ---------------- K4: scatter back to token positions -----------------------
__global__ void __launch_bounds__(256) k_scatter(
    const int* __restrict__ utter, float* __restrict__ out)
{
    int v = blockIdx.x * 256 + threadIdx.x;
    int m = v / 192;
    int h4 = v - m * 192;
    int u = __ldg(utter + m);
    float4 o = make_float4(0.f, 0.f, 0.f, 0.f);
    if (u != 0) {
        int idx = u > 0 ? u - 1 : -u - 1;
        if (idx > 31) idx = 31;
        int bb = m >> 11;
        float4 gv = *(const float4*)(g_emb + (bb * NU + idx) * HDIM + h4 * 4);
        float sc = u > 0 ? 1.f : 2.f;
        o.x = gv.x * sc; o.y = gv.y * sc; o.z = gv.z * sc; o.w = gv.w * sc;
    }
    ((float4*)out)[v] = o;
}

// ---------------- launch -----------------------------------------------------
extern "C" void kernel_launch(void* const* d_in, const int* in_sizes, int n_in,
                              void* d_out, int out_size)
{
    const float* X     = (const float*)d_in[0];
    const float* Wihf  = (const float*)d_in[1];
    const float* Whhf  = (const float*)d_in[2];
    const float* bihf  = (const float*)d_in[3];
    const float* bhhf  = (const float*)d_in[4];
    const float* Wihb  = (const float*)d_in[5];
    const float* Whhb  = (const float*)d_in[6];
    const float* bihb  = (const float*)d_in[7];
    const float* bhhb  = (const float*)d_in[8];
    const float* tw    = (const float*)d_in[9];
    const float* tb    = (const float*)d_in[10];
    const float* table = (const float*)d_in[11];
    const int*   utter = (const int*)d_in[12];

    // 1 pad: ncu capture (launch #4) lands on k_lstm
    k_pad<<<1, 32>>>();
    k_reset<<<16, 256>>>();
    k_gemm<<<dim3(12, 128, 2), 256>>>(X, Wihf, Wihb, bihf, bhhf, bihb, bhhb);
    k_lstm<<<128, 256>>>(Whhf, Whhb, utter);
    k_route<<<256, 256>>>(tw, tb, table);
    k_scatter<<<12288, 256>>>(utter, (float*)d_out);
}